// round 5
// baseline (speedup 1.0000x reference)
#include <cuda_runtime.h>

#define DATA_DIM 512
#define BASIS_DIM 64
#define N_ROWS 2048
#define N_SPANS 61
#define THREADS 512
#define GRID 148
#define A_PITCH 65   // padded smem row stride (floats): conflict-free staging stores

// dynamic smem layout (floats):
//   A_s   : [0, DATA_DIM*A_PITCH)            padded row-major copy of A
//   W     : [W_OFF, W_OFF + 7*4*4)           per-class basis-weight cubics (float4[7][4])
//   ws    : [WS_OFF, WS_OFF + 2*16)          double-buffered reduction scratch
#define W_OFF   (DATA_DIM * A_PITCH)          // 33280, 16B-aligned
#define WS_OFF  (W_OFF + 7 * 4 * 4)           // +112
#define SMEM_FLOATS (WS_OFF + 2 * 16)
#define SMEM_BYTES  (SMEM_FLOATS * 4)

// Clamped open-uniform knots: t[g] = clamp(g-3, 0, 61) / 61
__device__ __forceinline__ float knotf(int g) {
    int j = g - 3;
    j = max(0, min(N_SPANS, j));
    return (float)j / (float)N_SPANS;
}

// de Boor weights (polynomial extension) of the 4 nonzero cubic basis funcs on
// span m, exact IEEE divides (runs 28 threads x 4 samples once per CTA).
__device__ float4 deboor_weights(float xx, int m) {
    int k = m + 3;
    float left1  = xx - knotf(k);
    float left2  = xx - knotf(k - 1);
    float left3  = xx - knotf(k - 2);
    float right1 = knotf(k + 1) - xx;
    float right2 = knotf(k + 2) - xx;
    float right3 = knotf(k + 3) - xx;

    float N0 = 1.0f, N1, N2, N3, saved, temp;
    temp = N0 / (right1 + left1);
    N0 = right1 * temp;  N1 = left1 * temp;
    temp = N0 / (right1 + left2);
    N0 = right1 * temp;  saved = left2 * temp;
    temp = N1 / (right2 + left1);
    N1 = saved + right2 * temp;  N2 = left1 * temp;
    temp = N0 / (right1 + left3);
    N0 = right1 * temp;  saved = left3 * temp;
    temp = N1 / (right2 + left2);
    N1 = saved + right2 * temp;  saved = left2 * temp;
    temp = N2 / (right3 + left1);
    N2 = saved + right3 * temp;  N3 = left1 * temp;
    return make_float4(N0, N1, N2, N3);
}

__global__ void __launch_bounds__(THREADS, 1)
bspline_fused_kernel(const float* __restrict__ x,
                     const float* __restrict__ A,
                     float* __restrict__ out) {
    extern __shared__ float smem[];
    float*  A_s = smem;
    float4* Wsm = reinterpret_cast<float4*>(smem + W_OFF);
    float*  ws  = smem + WS_OFF;

    const int tid  = threadIdx.x;
    const int wid  = tid >> 5;
    const int lane = tid & 31;

    // ---- stage A into padded smem (coalesced float4 loads) ----
    const float4* Ag = reinterpret_cast<const float4*>(A);
    #pragma unroll
    for (int k = 0; k < (DATA_DIM * BASIS_DIM / 4) / THREADS; k++) {
        int f4 = k * THREADS + tid;          // float4 index into A
        float4 v = Ag[f4];
        int i = f4 >> 4;                      // dim   (16 float4 per row)
        int j = (f4 & 15) << 2;               // basis column
        float* dst = &A_s[i * A_PITCH + j];
        dst[0] = v.x; dst[1] = v.y; dst[2] = v.z; dst[3] = v.w;
    }

    // ---- build the 7 boundary-class weight cubics (28 threads) ----
    // class c: m<3 -> c=m; interior -> 3; m>57 -> m-54
    if (tid < 28) {
        int c = tid >> 2, j = tid & 3;
        int m_rep = (c < 3) ? c : ((c == 3) ? 30 : c + 54);
        float f[4];
        #pragma unroll
        for (int s = 0; s < 4; s++) {
            float xs = (float)(3 * m_rep + s) / (3.0f * (float)N_SPANS);
            float4 w = deboor_weights(xs, m_rep);
            f[s] = (j == 0) ? w.x : (j == 1) ? w.y : (j == 2) ? w.z : w.w;
        }
        // exact inverse Vandermonde at nodes {0, 1/3, 2/3, 1}
        float c0 = f[0];
        float c1 = -5.5f * f[0] +  9.0f * f[1] -  4.5f * f[2] +        f[3];
        float c2 =  9.0f * f[0] - 22.5f * f[1] + 18.0f * f[2] - 4.5f * f[3];
        float c3 = -4.5f * f[0] + 13.5f * f[1] - 13.5f * f[2] + 4.5f * f[3];
        Wsm[c * 4 + j] = make_float4(c0, c1, c2, c3);
    }

    // prefetch first row's x while staging settles
    float xcur = x[(size_t)blockIdx.x * DATA_DIM + tid];
    __syncthreads();

    int par = 0;
    for (int row = blockIdx.x; row < N_ROWS; row += GRID) {
        // prefetch next row's x (hides DRAM latency behind this row's compute)
        float xnext = 0.0f;
        int nrow = row + GRID;
        if (nrow < N_ROWS) xnext = x[(size_t)nrow * DATA_DIM + tid];

        // span + local coordinate
        float t = xcur * (float)N_SPANS;
        int m = max(0, min(N_SPANS - 1, (int)t));
        float u = t - (float)m;
        int c = (m < 3) ? m : ((m > 57) ? m - 54 : 3);

        // basis weights via per-class cubics (broadcast LDS.128 reads)
        float4 p0 = Wsm[c * 4 + 0];
        float4 p1 = Wsm[c * 4 + 1];
        float4 p2 = Wsm[c * 4 + 2];
        float4 p3 = Wsm[c * 4 + 3];
        float w0 = fmaf(fmaf(fmaf(p0.w, u, p0.z), u, p0.y), u, p0.x);
        float w1 = fmaf(fmaf(fmaf(p1.w, u, p1.z), u, p1.y), u, p1.x);
        float w2 = fmaf(fmaf(fmaf(p2.w, u, p2.z), u, p2.y), u, p2.x);
        float w3 = fmaf(fmaf(fmaf(p3.w, u, p3.z), u, p3.y), u, p3.x);

        // smem gather of A[tid][m..m+3]
        const float* a = &A_s[tid * A_PITCH + m];
        float partial = fmaf(w0, a[0], fmaf(w1, a[1], fmaf(w2, a[2], w3 * a[3])));

        // warp reduce
        #pragma unroll
        for (int o = 16; o > 0; o >>= 1)
            partial += __shfl_xor_sync(0xFFFFFFFFu, partial, o);
        if (lane == 0) ws[par * 16 + wid] = partial;
        __syncthreads();

        if (wid == 0) {
            float v = (lane < 16) ? ws[par * 16 + lane] : 0.0f;
            #pragma unroll
            for (int o = 8; o > 0; o >>= 1)
                v += __shfl_xor_sync(0xFFFFFFFFu, v, o);
            if (lane == 0)
                out[row] = 1.0f / (1.0f + __expf(-v));
        }

        xcur = xnext;
        par ^= 1;
    }
}

extern "C" void kernel_launch(void* const* d_in, const int* in_sizes, int n_in,
                              void* d_out, int out_size) {
    // Disambiguate by element count: x is 2048*512, A is 512*64.
    const float* x = (const float*)d_in[0];
    const float* A = (const float*)d_in[1];
    if (n_in >= 2 && in_sizes[0] == DATA_DIM * BASIS_DIM &&
        in_sizes[1] == N_ROWS * DATA_DIM) {
        x = (const float*)d_in[1];
        A = (const float*)d_in[0];
    }
    float* out = (float*)d_out;  // [2048]

    static bool attr_set = false;
    if (!attr_set) {
        cudaFuncSetAttribute(bspline_fused_kernel,
                             cudaFuncAttributeMaxDynamicSharedMemorySize,
                             SMEM_BYTES);
        attr_set = true;
    }
    bspline_fused_kernel<<<GRID, THREADS, SMEM_BYTES>>>(x, A, out);
}

// round 8
// speedup vs baseline: 1.2609x; 1.2609x over previous
#include <cuda_runtime.h>

#define DATA_DIM 512
#define BASIS_DIM 64
#define N_ROWS 2048
#define N_SPANS 61
#define THREADS 512
#define ROWS_PER_CTA 16
#define GRID (N_ROWS / ROWS_PER_CTA)   // 128
#define X_PITCH 514                     // padded: conflict-free column reads
#define NWARPS (THREADS / 32)           // 16

// Clamped open-uniform knots: t[g] = clamp(g-3, 0, 61) / 61
__device__ __forceinline__ float knotf(int g) {
    int j = g - 3;
    j = max(0, min(N_SPANS, j));
    return (float)j / (float)N_SPANS;
}

// de Boor weights (polynomial extension) on span m, exact IEEE divides.
// Runs on 28 threads once per CTA. Validated in R4/R5 (rel_err ~5e-7).
__device__ float4 deboor_weights(float xx, int m) {
    int k = m + 3;
    float left1  = xx - knotf(k);
    float left2  = xx - knotf(k - 1);
    float left3  = xx - knotf(k - 2);
    float right1 = knotf(k + 1) - xx;
    float right2 = knotf(k + 2) - xx;
    float right3 = knotf(k + 3) - xx;

    float N0 = 1.0f, N1, N2, N3, saved, temp;
    temp = N0 / (right1 + left1);
    N0 = right1 * temp;  N1 = left1 * temp;
    temp = N0 / (right1 + left2);
    N0 = right1 * temp;  saved = left2 * temp;
    temp = N1 / (right2 + left1);
    N1 = saved + right2 * temp;  N2 = left1 * temp;
    temp = N0 / (right1 + left3);
    N0 = right1 * temp;  saved = left3 * temp;
    temp = N1 / (right2 + left2);
    N1 = saved + right2 * temp;  saved = left2 * temp;
    temp = N2 / (right3 + left1);
    N2 = saved + right3 * temp;  N3 = left1 * temp;
    return make_float4(N0, N1, N2, N3);
}

__global__ void __launch_bounds__(THREADS, 1)
bspline_rowpar_kernel(const float* __restrict__ x,
                      const float* __restrict__ A,
                      float* __restrict__ out) {
    __shared__ float  x_s[ROWS_PER_CTA * X_PITCH];   // 16 rows x 512 dims, padded
    __shared__ float4 Wsm[7 * 4];                    // 7 boundary-class weight cubics
    __shared__ float  part[NWARPS * 17];             // per-warp per-row partials (pad 17)

    const int tid  = threadIdx.x;
    const int wid  = tid >> 5;
    const int lane = tid & 31;
    const int r    = lane & 15;      // row within CTA tile
    const int hi   = lane >> 4;      // dim parity within warp
    const int rowbase = blockIdx.x * ROWS_PER_CTA;

    // ---- stage x tile: coalesced float4 global reads -> padded smem ----
    const float4* xg = reinterpret_cast<const float4*>(x + (size_t)rowbase * DATA_DIM);
    #pragma unroll
    for (int k = 0; k < (ROWS_PER_CTA * DATA_DIM / 4) / THREADS; k++) {
        int f4 = k * THREADS + tid;          // 0 .. 2047
        float4 v = xg[f4];
        int rr = f4 >> 7;                    // 128 float4 per row
        int jj = (f4 & 127) << 2;
        float* d = &x_s[rr * X_PITCH + jj];
        d[0] = v.x; d[1] = v.y; d[2] = v.z; d[3] = v.w;
    }

    // ---- build 7 boundary-class weight cubics (28 threads) ----
    // class c: m<3 -> m ; interior -> 3 ; m>57 -> m-54
    if (tid < 28) {
        int c = tid >> 2, j = tid & 3;
        int m_rep = (c < 3) ? c : ((c == 3) ? 30 : c + 54);
        float f[4];
        #pragma unroll
        for (int s = 0; s < 4; s++) {
            float xs = (float)(3 * m_rep + s) / (3.0f * (float)N_SPANS);
            float4 w = deboor_weights(xs, m_rep);
            f[s] = (j == 0) ? w.x : (j == 1) ? w.y : (j == 2) ? w.z : w.w;
        }
        // exact inverse Vandermonde at nodes {0, 1/3, 2/3, 1}
        float c0 = f[0];
        float c1 = -5.5f * f[0] +  9.0f * f[1] -  4.5f * f[2] +        f[3];
        float c2 =  9.0f * f[0] - 22.5f * f[1] + 18.0f * f[2] - 4.5f * f[3];
        float c3 = -4.5f * f[0] + 13.5f * f[1] - 13.5f * f[2] + 4.5f * f[3];
        Wsm[c * 4 + j] = make_float4(c0, c1, c2, c3);
    }
    __syncthreads();

    // ---- main loop: warp wid owns dims [wid*32, wid*32+32); lane = (row, parity) ----
    // Thread handles dim i = wid*32 + 2*k + hi for k = 0..15; accumulates row r's sum.
    float acc = 0.0f;
    const int dimbase = wid * 32 + hi;
    const float* xrow = &x_s[r * X_PITCH];

    #pragma unroll
    for (int k = 0; k < 16; k++) {
        int i = dimbase + 2 * k;
        float xx = xrow[i];

        float t = xx * (float)N_SPANS;
        int m = max(0, min(N_SPANS - 1, (int)t));
        float u = t - (float)m;
        int c = (m < 3) ? m : ((m > 57) ? m - 54 : 3);

        float4 p0 = Wsm[c * 4 + 0];
        float4 p1 = Wsm[c * 4 + 1];
        float4 p2 = Wsm[c * 4 + 2];
        float4 p3 = Wsm[c * 4 + 3];
        float w0 = fmaf(fmaf(fmaf(p0.w, u, p0.z), u, p0.y), u, p0.x);
        float w1 = fmaf(fmaf(fmaf(p1.w, u, p1.z), u, p1.y), u, p1.x);
        float w2 = fmaf(fmaf(fmaf(p2.w, u, p2.z), u, p2.y), u, p2.x);
        float w3 = fmaf(fmaf(fmaf(p3.w, u, p3.z), u, p3.y), u, p3.x);

        // half-warp shares A row i -> gather touches ~2-4 lines, L1-hot
        const float* a = A + i * BASIS_DIM + m;
        acc = fmaf(w0, __ldg(a + 0),
              fmaf(w1, __ldg(a + 1),
              fmaf(w2, __ldg(a + 2),
              fmaf(w3, __ldg(a + 3), acc))));
    }

    // ---- reduce: fold dim-parity halves, then across 16 warps ----
    acc += __shfl_xor_sync(0xFFFFFFFFu, acc, 16);   // combine hi=0 / hi=1
    if (lane < 16) part[wid * 17 + r] = acc;
    __syncthreads();

    if (tid < ROWS_PER_CTA) {
        float s = 0.0f;
        #pragma unroll
        for (int j = 0; j < NWARPS; j++)
            s += part[j * 17 + tid];
        out[rowbase + tid] = 1.0f / (1.0f + __expf(-s));
    }
}

extern "C" void kernel_launch(void* const* d_in, const int* in_sizes, int n_in,
                              void* d_out, int out_size) {
    // Disambiguate by element count: x is 2048*512, A is 512*64.
    const float* x = (const float*)d_in[0];
    const float* A = (const float*)d_in[1];
    if (n_in >= 2 && in_sizes[0] == DATA_DIM * BASIS_DIM &&
        in_sizes[1] == N_ROWS * DATA_DIM) {
        x = (const float*)d_in[1];
        A = (const float*)d_in[0];
    }
    float* out = (float*)d_out;  // [2048]
    bspline_rowpar_kernel<<<GRID, THREADS>>>(x, A, out);
}